// round 6
// baseline (speedup 1.0000x reference)
#include <cuda_runtime.h>
#include <cuda_bf16.h>
#include <math.h>
#include <stdint.h>

// Problem constants
#define B_ 512
#define T_ 256
#define H_ 512
#define E_ 10
#define V_ 10000
#define C_ 10
#define NGATE 4
#define N_TOT (NGATE * H_)   // 2048; layout n = 4*j + gate (gates interleaved)

// ---------------------------------------------------------------------------
// Device-global state & scratch (no allocations allowed)
// ---------------------------------------------------------------------------
__device__ float g_h[B_ * H_];
__device__ float g_c[B_ * H_];
__device__ __nv_bfloat16 g_hhi[2][B_ * H_];   // ping-pong (cross-block hazard)
__device__ __nv_bfloat16 g_hlo[2][B_ * H_];
__device__ __nv_bfloat16 g_Wthi[N_TOT * H_];  // W^T split-hi: [n=4j+g][k]
__device__ __nv_bfloat16 g_Wtlo[N_TOT * H_];  // W^T split-lo

// ---------------------------------------------------------------------------
// One-time (per launch) weight transpose + bf16 hi/lo split.
// g_Wt[(4*j + g)][k] = Wh_g[k][j]
// ---------------------------------------------------------------------------
__global__ void prep_weights_kernel(
    const float* __restrict__ Wgh, const float* __restrict__ Wih,
    const float* __restrict__ Wfh, const float* __restrict__ Woh)
{
    __shared__ float tile[32][33];
    const float* const W[4] = {Wgh, Wih, Wfh, Woh};
    const int g = blockIdx.z;
    const int j0 = blockIdx.x * 32;
    const int k0 = blockIdx.y * 32;
    const int tx = threadIdx.x, ty = threadIdx.y;

    tile[ty][tx] = W[g][(k0 + ty) * H_ + j0 + tx];
    __syncthreads();

    float w = tile[tx][ty];                       // = W[k0+tx][j0+ty]
    __nv_bfloat16 hi = __float2bfloat16(w);
    __nv_bfloat16 lo = __float2bfloat16(w - __bfloat162float(hi));
    int n = 4 * (j0 + ty) + g;
    g_Wthi[n * H_ + k0 + tx] = hi;
    g_Wtlo[n * H_ + k0 + tx] = lo;
}

__global__ void init_state_kernel() {
    int i = blockIdx.x * blockDim.x + threadIdx.x;
    if (i < B_ * H_) {
        g_h[i] = 0.0f;
        g_c[i] = 0.0f;
        g_hhi[0][i] = __float2bfloat16(0.0f);
        g_hlo[0][i] = __float2bfloat16(0.0f);
    }
}

__device__ __forceinline__ void cp16(void* smem_dst, const void* gmem_src) {
    uint32_t s = (uint32_t)__cvta_generic_to_shared(smem_dst);
    asm volatile("cp.async.cg.shared.global [%0], [%1], 16;" :: "r"(s), "l"(gmem_src));
}

__device__ __forceinline__ void mma_bf16(
    float c[4], const uint32_t a[4], uint32_t b0, uint32_t b1)
{
    asm volatile(
        "mma.sync.aligned.m16n8k16.row.col.f32.bf16.bf16.f32 "
        "{%0,%1,%2,%3}, {%4,%5,%6,%7}, {%8,%9}, {%0,%1,%2,%3};"
        : "+f"(c[0]), "+f"(c[1]), "+f"(c[2]), "+f"(c[3])
        : "r"(a[0]), "r"(a[1]), "r"(a[2]), "r"(a[3]), "r"(b0), "r"(b1));
}

// ---------------------------------------------------------------------------
// Fully fused LSTM step:
//   mainloop: z = h @ Wt^T (split-bf16, 3-term MMA, cp.async double-buffered)
//   epilogue: accs -> smem -> + x-proj + bias -> activations -> c/h update
//             -> write h, c, and bf16 hi/lo split of h (next step's A operand)
// Block tile 64(M) x 128(N = 32 j x 4 gates). 8 warps. Grid (16, 8).
// ---------------------------------------------------------------------------
#define GBM 64
#define GBN 128
#define GKC 32
#define APAD 40
#define NT 256
#define A_ELEMS (2 * 2 * GBM * APAD)            // 10240 bf16
#define B_ELEMS (2 * 2 * GBN * APAD)            // 20480 bf16
#define MAIN_SMEM_BYTES ((A_ELEMS + B_ELEMS) * 2)   // 61440
#define ZPAD 132
#define EXTRA_FLOATS (GBM * E_ + NGATE * E_ * 32 + NGATE * 32)  // 640+1280+128
#define FUSED_SMEM_BYTES (MAIN_SMEM_BYTES + EXTRA_FLOATS * 4)   // 69632

__global__ void __launch_bounds__(NT) lstm_fused_step(
    int t, int src,
    const int* __restrict__ x, const float* __restrict__ emb,
    const float* __restrict__ Wgx, const float* __restrict__ Wix,
    const float* __restrict__ Wfx, const float* __restrict__ Wox,
    const float* __restrict__ bg, const float* __restrict__ bi,
    const float* __restrict__ bf_, const float* __restrict__ bo)
{
    extern __shared__ char smem_raw[];
    __nv_bfloat16* const Asm = (__nv_bfloat16*)smem_raw;
    __nv_bfloat16* const Bsm = Asm + A_ELEMS;
    float* const z_s    = (float*)smem_raw;                    // epilogue alias
    float* const xe_s   = (float*)(smem_raw + MAIN_SMEM_BYTES);// [64][E_]
    float* const xw_s   = xe_s + GBM * E_;                     // [4][E_][32]
    float* const bias_s = xw_s + NGATE * E_ * 32;              // [4][32]

    const int tid = threadIdx.x;
    const int bn = blockIdx.x * GBN;    // col base (n = 4j+g)
    const int bj = blockIdx.x * 32;     // j base
    const int bb = blockIdx.y * GBM;    // batch base
    const int w = tid >> 5;
    const int lane = tid & 31;
    const int gid = lane >> 2;
    const int tig = lane & 3;
    const int wm = (w >> 1) * 16;
    const int wn = (w & 1) * 64;

    const __nv_bfloat16* __restrict__ hhi = g_hhi[src];
    const __nv_bfloat16* __restrict__ hlo = g_hlo[src];
    __nv_bfloat16* __restrict__ hhi_out = g_hhi[src ^ 1];
    __nv_bfloat16* __restrict__ hlo_out = g_hlo[src ^ 1];

    auto aoff = [&](int buf, int hl, int r, int c) {
        return ((buf * 2 + hl) * GBM + r) * APAD + c;
    };
    auto boff = [&](int buf, int hl, int r, int c) {
        return ((buf * 2 + hl) * GBN + r) * APAD + c;
    };
    auto load_chunk = [&](int buf, int k0) {
        int r = tid >> 2, s = (tid & 3) * 8;
        cp16(&Asm[aoff(buf, 0, r, s)], &hhi[(bb + r) * H_ + k0 + s]);
        cp16(&Asm[aoff(buf, 1, r, s)], &hlo[(bb + r) * H_ + k0 + s]);
        #pragma unroll
        for (int half = 0; half < 2; half++) {
            int idx2 = tid + half * NT;
            int br = idx2 >> 2, bs = (idx2 & 3) * 8;
            cp16(&Bsm[boff(buf, 0, br, bs)], &g_Wthi[(bn + br) * H_ + k0 + bs]);
            cp16(&Bsm[boff(buf, 1, br, bs)], &g_Wtlo[(bn + br) * H_ + k0 + bs]);
        }
        asm volatile("cp.async.commit_group;");
    };

    load_chunk(0, 0);

    // ---- stage epilogue operands (disjoint smem; overlaps pipeline) ----
    for (int i = tid; i < GBM * E_; i += NT) {
        int r = i / E_, e = i % E_;
        int idx = x[(bb + r) * T_ + t];
        idx = min(max(idx, 0), V_ - 1);
        xe_s[r * E_ + e] = emb[idx * E_ + e];
    }
    {
        const float* const Wx[4] = {Wgx, Wix, Wfx, Wox};
        for (int i = tid; i < NGATE * E_ * 32; i += NT) {
            int g = i / (E_ * 32), rem = i % (E_ * 32);
            int e = rem / 32, jl = rem % 32;
            xw_s[i] = Wx[g][e * H_ + bj + jl];
        }
        const float* const bptr[4] = {bg, bi, bf_, bo};
        if (tid < NGATE * 32) {
            int g = tid / 32, jl = tid % 32;
            bias_s[tid] = bptr[g][bj + jl];
        }
    }

    float acc[8][4];
    #pragma unroll
    for (int nf = 0; nf < 8; nf++)
        #pragma unroll
        for (int v = 0; v < 4; v++) acc[nf][v] = 0.0f;

    // ---- recurrent GEMM mainloop ----
    const int NCH = H_ / GKC;   // 16
    #pragma unroll 1
    for (int kt = 0; kt < NCH; kt++) {
        asm volatile("cp.async.wait_group 0;" ::: "memory");
        __syncthreads();
        if (kt + 1 < NCH) load_chunk((kt + 1) & 1, (kt + 1) * GKC);

        const int buf = kt & 1;
        #pragma unroll
        for (int kk = 0; kk < GKC; kk += 16) {
            uint32_t ahi[4], alo[4];
            const int ar0 = wm + gid, ac0 = kk + 2 * tig;
            ahi[0] = *(const uint32_t*)&Asm[aoff(buf, 0, ar0,     ac0)];
            ahi[1] = *(const uint32_t*)&Asm[aoff(buf, 0, ar0 + 8, ac0)];
            ahi[2] = *(const uint32_t*)&Asm[aoff(buf, 0, ar0,     ac0 + 8)];
            ahi[3] = *(const uint32_t*)&Asm[aoff(buf, 0, ar0 + 8, ac0 + 8)];
            alo[0] = *(const uint32_t*)&Asm[aoff(buf, 1, ar0,     ac0)];
            alo[1] = *(const uint32_t*)&Asm[aoff(buf, 1, ar0 + 8, ac0)];
            alo[2] = *(const uint32_t*)&Asm[aoff(buf, 1, ar0,     ac0 + 8)];
            alo[3] = *(const uint32_t*)&Asm[aoff(buf, 1, ar0 + 8, ac0 + 8)];

            #pragma unroll
            for (int nf = 0; nf < 8; nf++) {
                const int brow = wn + nf * 8 + gid;
                uint32_t bhi0 = *(const uint32_t*)&Bsm[boff(buf, 0, brow, ac0)];
                uint32_t bhi1 = *(const uint32_t*)&Bsm[boff(buf, 0, brow, ac0 + 8)];
                uint32_t blo0 = *(const uint32_t*)&Bsm[boff(buf, 1, brow, ac0)];
                uint32_t blo1 = *(const uint32_t*)&Bsm[boff(buf, 1, brow, ac0 + 8)];
                mma_bf16(acc[nf], ahi, bhi0, bhi1);   // hi*hi
                mma_bf16(acc[nf], ahi, blo0, blo1);   // hi*lo
                mma_bf16(acc[nf], alo, bhi0, bhi1);   // lo*hi
            }
        }
        __syncthreads();
    }

    // ---- spill accs to smem (aliased over dead A/B buffers) ----
    {
        const int row_l = wm + gid;
        #pragma unroll
        for (int nf = 0; nf < 8; nf++) {
            const int col = wn + nf * 8 + 2 * tig;
            *(float2*)&z_s[row_l * ZPAD + col] =
                make_float2(acc[nf][0], acc[nf][1]);
            *(float2*)&z_s[(row_l + 8) * ZPAD + col] =
                make_float2(acc[nf][2], acc[nf][3]);
        }
    }
    __syncthreads();

    // ---- fused pointwise: x-proj + bias + activations + c/h update ----
    #pragma unroll
    for (int rep = 0; rep < (GBM * 32) / NT; rep++) {   // 8 reps
        const int elem = tid + rep * NT;
        const int r = elem >> 5, jl = elem & 31;
        const int gr = bb + r, gj = bj + jl;

        float zg = z_s[r * ZPAD + 4 * jl + 0] + bias_s[0 * 32 + jl];
        float zi = z_s[r * ZPAD + 4 * jl + 1] + bias_s[1 * 32 + jl];
        float zf = z_s[r * ZPAD + 4 * jl + 2] + bias_s[2 * 32 + jl];
        float zo = z_s[r * ZPAD + 4 * jl + 3] + bias_s[3 * 32 + jl];

        #pragma unroll
        for (int e = 0; e < E_; e++) {
            float xv = xe_s[r * E_ + e];
            zg += xv * xw_s[0 * E_ * 32 + e * 32 + jl];
            zi += xv * xw_s[1 * E_ * 32 + e * 32 + jl];
            zf += xv * xw_s[2 * E_ * 32 + e * 32 + jl];
            zo += xv * xw_s[3 * E_ * 32 + e * 32 + jl];
        }

        float gg = tanhf(zg);
        float ii = 1.0f / (1.0f + __expf(-zi));
        float ff = 1.0f / (1.0f + __expf(-zf));
        float oo = 1.0f / (1.0f + __expf(-zo));

        float cn = gg * ii + g_c[gr * H_ + gj] * ff;
        float hn = tanhf(cn) * oo;

        g_c[gr * H_ + gj] = cn;
        g_h[gr * H_ + gj] = hn;
        __nv_bfloat16 hi = __float2bfloat16(hn);
        hhi_out[gr * H_ + gj] = hi;
        hlo_out[gr * H_ + gj] = __float2bfloat16(hn - __bfloat162float(hi));
    }
}

// ---------------------------------------------------------------------------
// Final projection: out[b,c] = h_T[b,:] @ Wph[:,c] + bp[c]
// ---------------------------------------------------------------------------
__global__ void proj_kernel(const float* __restrict__ Wph,
                            const float* __restrict__ bp, float* __restrict__ out) {
    int i = blockIdx.x * blockDim.x + threadIdx.x;
    if (i >= B_ * C_) return;
    int b = i / C_;
    int c = i % C_;
    float acc = bp[c];
    #pragma unroll 8
    for (int k = 0; k < H_; k++) {
        acc += g_h[b * H_ + k] * Wph[k * C_ + c];
    }
    out[i] = acc;
}

// ---------------------------------------------------------------------------
// Launch sequence (graph-capturable, single stream)
// ---------------------------------------------------------------------------
extern "C" void kernel_launch(void* const* d_in, const int* in_sizes, int n_in,
                              void* d_out, int out_size) {
    const int* x        = (const int*)d_in[0];       // int32 (JAX downcasts int64)
    const float* emb    = (const float*)d_in[1];
    const float* Wgx    = (const float*)d_in[2];
    const float* Wgh    = (const float*)d_in[3];
    const float* bg     = (const float*)d_in[4];
    const float* Wix    = (const float*)d_in[5];
    const float* Wih    = (const float*)d_in[6];
    const float* bi     = (const float*)d_in[7];
    const float* Wfx    = (const float*)d_in[8];
    const float* Wfh    = (const float*)d_in[9];
    const float* bf_    = (const float*)d_in[10];
    const float* Wox    = (const float*)d_in[11];
    const float* Woh    = (const float*)d_in[12];
    const float* bo     = (const float*)d_in[13];
    const float* Wph    = (const float*)d_in[14];
    const float* bp     = (const float*)d_in[15];
    float* out          = (float*)d_out;

    static bool attr_set = false;
    if (!attr_set) {
        cudaFuncSetAttribute(lstm_fused_step,
                             cudaFuncAttributeMaxDynamicSharedMemorySize,
                             FUSED_SMEM_BYTES);
        attr_set = true;
    }

    {
        dim3 tgrid(H_ / 32, H_ / 32, NGATE);
        dim3 tblk(32, 32);
        prep_weights_kernel<<<tgrid, tblk>>>(Wgh, Wih, Wfh, Woh);
    }
    init_state_kernel<<<(B_ * H_ + 255) / 256, 256>>>();

    dim3 ggrid(N_TOT / GBN, B_ / GBM);   // (16, 8) = 128 blocks
    for (int t = 0; t < T_; t++) {
        lstm_fused_step<<<ggrid, NT, FUSED_SMEM_BYTES>>>(
            t, t & 1, x, emb, Wgx, Wix, Wfx, Wox, bg, bi, bf_, bo);
    }

    proj_kernel<<<(B_ * C_ + 255) / 256, 256>>>(Wph, bp, out);
}

// round 7
// speedup vs baseline: 1.0984x; 1.0984x over previous
#include <cuda_runtime.h>
#include <cuda_bf16.h>
#include <math.h>
#include <stdint.h>

// Problem constants
#define B_ 512
#define T_ 256
#define H_ 512
#define E_ 10
#define V_ 10000
#define C_ 10
#define NGATE 4
#define N_TOT (NGATE * H_)   // 2048; layout n = 4*j + gate (gates interleaved)

// ---------------------------------------------------------------------------
// Device-global state & scratch (no allocations allowed)
// ---------------------------------------------------------------------------
__device__ float g_h[B_ * H_];
__device__ float g_c[B_ * H_];
__device__ __nv_bfloat16 g_hhi[2][B_ * H_];   // ping-pong (cross-block hazard)
__device__ __nv_bfloat16 g_hlo[2][B_ * H_];
__device__ __nv_bfloat16 g_Wthi[N_TOT * H_];  // W^T split-hi: [n=4j+g][k]
__device__ __nv_bfloat16 g_Wtlo[N_TOT * H_];  // W^T split-lo

// ---------------------------------------------------------------------------
// One-time weight transpose + bf16 hi/lo split: g_Wt[(4j+g)][k] = Wh_g[k][j]
// ---------------------------------------------------------------------------
__global__ void prep_weights_kernel(
    const float* __restrict__ Wgh, const float* __restrict__ Wih,
    const float* __restrict__ Wfh, const float* __restrict__ Woh)
{
    __shared__ float tile[32][33];
    const float* const W[4] = {Wgh, Wih, Wfh, Woh};
    const int g = blockIdx.z;
    const int j0 = blockIdx.x * 32;
    const int k0 = blockIdx.y * 32;
    const int tx = threadIdx.x, ty = threadIdx.y;

    tile[ty][tx] = W[g][(k0 + ty) * H_ + j0 + tx];
    __syncthreads();

    float w = tile[tx][ty];                       // = W[k0+tx][j0+ty]
    __nv_bfloat16 hi = __float2bfloat16(w);
    __nv_bfloat16 lo = __float2bfloat16(w - __bfloat162float(hi));
    int n = 4 * (j0 + ty) + g;
    g_Wthi[n * H_ + k0 + tx] = hi;
    g_Wtlo[n * H_ + k0 + tx] = lo;
}

__global__ void init_state_kernel() {
    int i = blockIdx.x * blockDim.x + threadIdx.x;
    if (i < B_ * H_) {
        g_h[i] = 0.0f;
        g_c[i] = 0.0f;
        g_hhi[0][i] = __float2bfloat16(0.0f);
        g_hlo[0][i] = __float2bfloat16(0.0f);
    }
}

__device__ __forceinline__ void cp16(void* smem_dst, const void* gmem_src) {
    uint32_t s = (uint32_t)__cvta_generic_to_shared(smem_dst);
    asm volatile("cp.async.cg.shared.global [%0], [%1], 16;" :: "r"(s), "l"(gmem_src));
}

__device__ __forceinline__ void ldm_x4(uint32_t r[4], uint32_t addr) {
    asm volatile("ldmatrix.sync.aligned.m8n8.x4.shared.b16 {%0,%1,%2,%3}, [%4];"
                 : "=r"(r[0]), "=r"(r[1]), "=r"(r[2]), "=r"(r[3]) : "r"(addr));
}

__device__ __forceinline__ void mma_bf16(
    float c[4], const uint32_t a[4], uint32_t b0, uint32_t b1)
{
    asm volatile(
        "mma.sync.aligned.m16n8k16.row.col.f32.bf16.bf16.f32 "
        "{%0,%1,%2,%3}, {%4,%5,%6,%7}, {%8,%9}, {%0,%1,%2,%3};"
        : "+f"(c[0]), "+f"(c[1]), "+f"(c[2]), "+f"(c[3])
        : "r"(a[0]), "r"(a[1]), "r"(a[2]), "r"(a[3]), "r"(b0), "r"(b1));
}

// ---------------------------------------------------------------------------
// Fully fused LSTM step. Block tile 64(M) x 128(N = 32 j x 4 gates),
// 16 warps (warp tile 16x32), k-chunks of 32, cp.async double-buffered,
// ldmatrix.x4 fragment loads, split-bf16 3-term MMA.
// Grid (2048/128, 512/64) = (16, 8) = 128 blocks, single wave, 4 warps/SMSP.
// ---------------------------------------------------------------------------
#define GBM 64
#define GBN 128
#define GKC 32
#define APAD 40
#define NT 512
#define A_ELEMS (2 * 2 * GBM * APAD)                 // 10240 bf16
#define B_ELEMS (2 * 2 * GBN * APAD)                 // 20480 bf16
#define MAIN_SMEM_BYTES ((A_ELEMS + B_ELEMS) * 2)    // 61440
#define A_BUF_STRIDE 10240   // bytes: 2hl*64*40*2
#define A_HL_STRIDE  5120
#define B_BUF_STRIDE 20480
#define B_HL_STRIDE  10240
#define ZPAD 132
#define EXTRA_FLOATS (GBM * E_ + NGATE * E_ * 32 + NGATE * 32)  // 2048
#define FUSED_SMEM_BYTES (MAIN_SMEM_BYTES + EXTRA_FLOATS * 4)   // 69632

__global__ void __launch_bounds__(NT) lstm_fused_step(
    int t, int src,
    const int* __restrict__ x, const float* __restrict__ emb,
    const float* __restrict__ Wgx, const float* __restrict__ Wix,
    const float* __restrict__ Wfx, const float* __restrict__ Wox,
    const float* __restrict__ bg, const float* __restrict__ bi,
    const float* __restrict__ bf_, const float* __restrict__ bo)
{
    extern __shared__ char smem_raw[];
    __nv_bfloat16* const Asm = (__nv_bfloat16*)smem_raw;
    __nv_bfloat16* const Bsm = Asm + A_ELEMS;
    float* const z_s    = (float*)smem_raw;                     // epilogue alias
    float* const xe_s   = (float*)(smem_raw + MAIN_SMEM_BYTES); // [64][E_]
    float* const xw_s   = xe_s + GBM * E_;                      // [4][E_][32]
    float* const bias_s = xw_s + NGATE * E_ * 32;               // [4][32]

    const int tid = threadIdx.x;
    const int bn = blockIdx.x * GBN;    // col base (n = 4j+g)
    const int bj = blockIdx.x * 32;     // j base
    const int bb = blockIdx.y * GBM;    // batch base
    const int w = tid >> 5;
    const int lane = tid & 31;
    const int gid = lane >> 2;
    const int tig = lane & 3;
    const int wm = (w >> 2) * 16;       // 4 m-groups
    const int wn = (w & 3) * 32;        // 4 n-groups

    const __nv_bfloat16* __restrict__ hhi = g_hhi[src];
    const __nv_bfloat16* __restrict__ hlo = g_hlo[src];
    __nv_bfloat16* __restrict__ hhi_out = g_hhi[src ^ 1];
    __nv_bfloat16* __restrict__ hlo_out = g_hlo[src ^ 1];

    // ldmatrix per-lane base addresses (bytes, shared space)
    const uint32_t Abase = (uint32_t)__cvta_generic_to_shared(Asm);
    const uint32_t Bbase = (uint32_t)__cvta_generic_to_shared(Bsm);
    const uint32_t a_addr = Abase +
        ((wm + ((lane >> 3) & 1) * 8 + (lane & 7)) * APAD + ((lane >> 4) & 1) * 8) * 2;
    const uint32_t b_addr0 = Bbase +
        ((wn + ((lane >> 4) & 1) * 8 + (lane & 7)) * APAD + ((lane >> 3) & 1) * 8) * 2;
    const uint32_t b_addr1 = b_addr0 + 16 * APAD * 2;   // +16 n rows

    auto aoff = [&](int buf, int hl, int r, int c) {
        return ((buf * 2 + hl) * GBM + r) * APAD + c;
    };
    auto boff = [&](int buf, int hl, int r, int c) {
        return ((buf * 2 + hl) * GBN + r) * APAD + c;
    };
    auto load_chunk = [&](int buf, int k0) {
        // A: 2 hl * 64r * 32k bf16 = 512 x 16B segs -> 1 per thread
        {
            int hl = tid >> 8, r = (tid >> 2) & 63, s = (tid & 3) * 8;
            const __nv_bfloat16* srcp = hl ? hlo : hhi;
            cp16(&Asm[aoff(buf, hl, r, s)], &srcp[(bb + r) * H_ + k0 + s]);
        }
        // B: 2 hl * 128r * 32k = 1024 segs -> 2 per thread
        #pragma unroll
        for (int half = 0; half < 2; half++) {
            int idx = tid + half * NT;
            int hl = idx >> 9, br = (idx >> 2) & 127, bs = (idx & 3) * 8;
            const __nv_bfloat16* srcp = hl ? g_Wtlo : g_Wthi;
            cp16(&Bsm[boff(buf, hl, br, bs)], &srcp[(bn + br) * H_ + k0 + bs]);
        }
        asm volatile("cp.async.commit_group;");
    };

    load_chunk(0, 0);

    // ---- stage epilogue operands (disjoint smem; overlaps pipeline) ----
    for (int i = tid; i < GBM * E_; i += NT) {
        int r = i / E_, e = i % E_;
        int idx = x[(bb + r) * T_ + t];
        idx = min(max(idx, 0), V_ - 1);
        xe_s[r * E_ + e] = emb[idx * E_ + e];
    }
    {
        const float* const Wx[4] = {Wgx, Wix, Wfx, Wox};
        for (int i = tid; i < NGATE * E_ * 32; i += NT) {
            int g = i / (E_ * 32), rem = i % (E_ * 32);
            int e = rem / 32, jl = rem % 32;
            xw_s[i] = Wx[g][e * H_ + bj + jl];
        }
        const float* const bptr[4] = {bg, bi, bf_, bo};
        if (tid < NGATE * 32) {
            int g = tid / 32, jl = tid % 32;
            bias_s[tid] = bptr[g][bj + jl];
        }
    }

    float acc[4][4];
    #pragma unroll
    for (int nf = 0; nf < 4; nf++)
        #pragma unroll
        for (int v = 0; v < 4; v++) acc[nf][v] = 0.0f;

    // ---- recurrent GEMM mainloop ----
    const int NCH = H_ / GKC;   // 16
    #pragma unroll 1
    for (int kt = 0; kt < NCH; kt++) {
        asm volatile("cp.async.wait_group 0;" ::: "memory");
        __syncthreads();
        if (kt + 1 < NCH) load_chunk((kt + 1) & 1, (kt + 1) * GKC);

        const uint32_t abuf = a_addr + (kt & 1) * A_BUF_STRIDE;
        const uint32_t bbuf0 = b_addr0 + (kt & 1) * B_BUF_STRIDE;
        const uint32_t bbuf1 = b_addr1 + (kt & 1) * B_BUF_STRIDE;

        #pragma unroll
        for (int kk = 0; kk < GKC; kk += 16) {
            uint32_t ahi[4], alo[4];
            ldm_x4(ahi, abuf + kk * 2);
            ldm_x4(alo, abuf + kk * 2 + A_HL_STRIDE);

            #pragma unroll
            for (int p = 0; p < 2; p++) {
                const uint32_t ba = (p ? bbuf1 : bbuf0) + kk * 2;
                uint32_t bh[4], bl[4];
                ldm_x4(bh, ba);
                ldm_x4(bl, ba + B_HL_STRIDE);
                mma_bf16(acc[2 * p],     ahi, bh[0], bh[1]);
                mma_bf16(acc[2 * p + 1], ahi, bh[2], bh[3]);
                mma_bf16(acc[2 * p],     ahi, bl[0], bl[1]);
                mma_bf16(acc[2 * p + 1], ahi, bl[2], bl[3]);
                mma_bf16(acc[2 * p],     alo, bh[0], bh[1]);
                mma_bf16(acc[2 * p + 1], alo, bh[2], bh[3]);
            }
        }
        __syncthreads();
    }

    // ---- spill accs to smem (aliased over dead A/B buffers) ----
    {
        const int row_l = wm + gid;
        #pragma unroll
        for (int nf = 0; nf < 4; nf++) {
            const int col = wn + nf * 8 + 2 * tig;
            *(float2*)&z_s[row_l * ZPAD + col] =
                make_float2(acc[nf][0], acc[nf][1]);
            *(float2*)&z_s[(row_l + 8) * ZPAD + col] =
                make_float2(acc[nf][2], acc[nf][3]);
        }
    }
    __syncthreads();

    // ---- fused pointwise: x-proj + bias + activations + c/h update ----
    #pragma unroll
    for (int rep = 0; rep < (GBM * 32) / NT; rep++) {   // 4 reps
        const int elem = tid + rep * NT;
        const int r = elem >> 5, jl = elem & 31;
        const int gr = bb + r, gj = bj + jl;

        float zg = z_s[r * ZPAD + 4 * jl + 0] + bias_s[0 * 32 + jl];
        float zi = z_s[r * ZPAD + 4 * jl + 1] + bias_s[1 * 32 + jl];
        float zf = z_s[r * ZPAD + 4 * jl + 2] + bias_s[2 * 32 + jl];
        float zo = z_s[r * ZPAD + 4 * jl + 3] + bias_s[3 * 32 + jl];

        #pragma unroll
        for (int e = 0; e < E_; e++) {
            float xv = xe_s[r * E_ + e];
            zg += xv * xw_s[0 * E_ * 32 + e * 32 + jl];
            zi += xv * xw_s[1 * E_ * 32 + e * 32 + jl];
            zf += xv * xw_s[2 * E_ * 32 + e * 32 + jl];
            zo += xv * xw_s[3 * E_ * 32 + e * 32 + jl];
        }

        float gg = tanhf(zg);
        float ii = 1.0f / (1.0f + __expf(-zi));
        float ff = 1.0f / (1.0f + __expf(-zf));
        float oo = 1.0f / (1.0f + __expf(-zo));

        float cn = gg * ii + g_c[gr * H_ + gj] * ff;
        float hn = tanhf(cn) * oo;

        g_c[gr * H_ + gj] = cn;
        g_h[gr * H_ + gj] = hn;
        __nv_bfloat16 hi = __float2bfloat16(hn);
        hhi_out[gr * H_ + gj] = hi;
        hlo_out[gr * H_ + gj] = __float2bfloat16(hn - __bfloat162float(hi));
    }
}

// ---------------------------------------------------------------------------
// Final projection: out[b,c] = h_T[b,:] @ Wph[:,c] + bp[c]
// ---------------------------------------------------------------------------
__global__ void proj_kernel(const float* __restrict__ Wph,
                            const float* __restrict__ bp, float* __restrict__ out) {
    int i = blockIdx.x * blockDim.x + threadIdx.x;
    if (i >= B_ * C_) return;
    int b = i / C_;
    int c = i % C_;
    float acc = bp[c];
    #pragma unroll 8
    for (int k = 0; k < H_; k++) {
        acc += g_h[b * H_ + k] * Wph[k * C_ + c];
    }
    out[i] = acc;
}

// ---------------------------------------------------------------------------
// Launch sequence (graph-capturable, single stream)
// ---------------------------------------------------------------------------
extern "C" void kernel_launch(void* const* d_in, const int* in_sizes, int n_in,
                              void* d_out, int out_size) {
    const int* x        = (const int*)d_in[0];       // int32 (JAX downcasts int64)
    const float* emb    = (const float*)d_in[1];
    const float* Wgx    = (const float*)d_in[2];
    const float* Wgh    = (const float*)d_in[3];
    const float* bg     = (const float*)d_in[4];
    const float* Wix    = (const float*)d_in[5];
    const float* Wih    = (const float*)d_in[6];
    const float* bi     = (const float*)d_in[7];
    const float* Wfx    = (const float*)d_in[8];
    const float* Wfh    = (const float*)d_in[9];
    const float* bf_    = (const float*)d_in[10];
    const float* Wox    = (const float*)d_in[11];
    const float* Woh    = (const float*)d_in[12];
    const float* bo     = (const float*)d_in[13];
    const float* Wph    = (const float*)d_in[14];
    const float* bp     = (const float*)d_in[15];
    float* out          = (float*)d_out;

    static bool attr_set = false;
    if (!attr_set) {
        cudaFuncSetAttribute(lstm_fused_step,
                             cudaFuncAttributeMaxDynamicSharedMemorySize,
                             FUSED_SMEM_BYTES);
        attr_set = true;
    }

    {
        dim3 tgrid(H_ / 32, H_ / 32, NGATE);
        dim3 tblk(32, 32);
        prep_weights_kernel<<<tgrid, tblk>>>(Wgh, Wih, Wfh, Woh);
    }
    init_state_kernel<<<(B_ * H_ + 255) / 256, 256>>>();

    dim3 ggrid(N_TOT / GBN, B_ / GBM);   // (16, 8) = 128 blocks
    for (int t = 0; t < T_; t++) {
        lstm_fused_step<<<ggrid, NT, FUSED_SMEM_BYTES>>>(
            t, t & 1, x, emb, Wgx, Wix, Wfx, Wox, bg, bi, bf_, bo);
    }

    proj_kernel<<<(B_ * C_ + 255) / 256, 256>>>(Wph, bp, out);
}